// round 8
// baseline (speedup 1.0000x reference)
#include <cuda_runtime.h>
#include <math.h>

// Problem dims: B=4 O=4 L=128 N=8 V=256 H=256, Ls=2L=256, BO=16, BON=128, NL=1024

// ---------------- scratch (device globals; no allocation allowed) ----------------
__device__ float g_stmt_in[16 * 256 * 256];
__device__ float g_xg_stmt[16 * 256 * 768];
__device__ float g_stmt_h[16 * 256 * 256];
__device__ float g_xg_docs[128 * 128 * 768];
__device__ float g_docs_h[128 * 128 * 256];
__device__ float g_hs0[16 * 256], g_hs1[16 * 256];
__device__ float g_hd0[128 * 256], g_hd1[128 * 256];
__device__ float g_match[128 * 256 * 128];
__device__ float g_p1[128 * 256 * 128];
__device__ float g_p2t[128 * 128 * 256];
__device__ float g_read_sum[128 * 256 * 256];
__device__ float g_doc_read[128 * 128 * 256];
__device__ float g_dri[128 * 128 * 512];
__device__ float g_mm[16 * 1024 * 1024];
__device__ float g_att[128 * 128 * 512];
__device__ float g_xg_sr[128 * 256 * 768];
__device__ float g_xg_dr[128 * 128 * 768];
__device__ float g_hsr0[128 * 256], g_hsr1[128 * 256];
__device__ float g_hdr0[128 * 256], g_hdr1[128 * 256];
__device__ float g_srmax[128 * 256], g_drmax[128 * 256];

// per-(slot, chunk) monotonic step flags: 64 slots x 8 chunks, 128B stride
__device__ unsigned g_flag[64 * 8 * 32];

// ---------------- init ----------------
__global__ void init_state() {
    int i = blockIdx.x * 256 + threadIdx.x;  // 32768 threads
    if (i < 64 * 8 * 32) g_flag[i] = 0u;
    if (i < 16 * 256) { g_hs0[i] = 0.f; g_hs1[i] = 0.f; }
    if (i < 128 * 256) {
        g_hd0[i] = 0.f;  g_hd1[i] = 0.f;
        g_hsr0[i] = 0.f; g_hsr1[i] = 0.f;
        g_hdr0[i] = 0.f; g_hdr1[i] = 0.f;
    }
}

// ---------------- build stmt = cat(question, answer) ----------------
__global__ void concat_stmt(const float* __restrict__ statement,
                            const float* __restrict__ answer) {
    int idx = blockIdx.x * 256 + threadIdx.x;  // 1048576
    int v = idx & 255;
    int s = (idx >> 8) & 255;
    int bo = idx >> 16;
    int b = bo >> 2;
    float val;
    if (s < 128) val = statement[(b * 128 + s) * 256 + v];
    else         val = answer[(bo * 128 + (s - 128)) * 256 + v];
    g_stmt_in[idx] = val;
}

// ---------------- dri = cat(docs, doc_read) ----------------
__global__ void concat_dri() {
    for (int idx = blockIdx.x * blockDim.x + threadIdx.x; idx < 128 * 128 * 512;
         idx += gridDim.x * blockDim.x) {
        int h = idx & 511;
        int rest = idx >> 9;
        g_dri[idx] = (h < 256) ? g_docs_h[rest * 256 + h]
                               : g_doc_read[rest * 256 + (h - 256)];
    }
}

// ---------------- tf32 tensor-core GEMM ----------------
__device__ __forceinline__ unsigned f2tf(float x) {
    unsigned r;
    asm("cvt.rna.tf32.f32 %0, %1;" : "=r"(r) : "f"(x));
    return r;
}

__device__ __forceinline__ void mma_tf32(float4& d, const unsigned* a, const unsigned* b) {
    asm volatile(
        "mma.sync.aligned.m16n8k8.row.col.f32.tf32.tf32.f32 "
        "{%0,%1,%2,%3}, {%4,%5,%6,%7}, {%8,%9}, {%0,%1,%2,%3};"
        : "+f"(d.x), "+f"(d.y), "+f"(d.z), "+f"(d.w)
        : "r"(a[0]), "r"(a[1]), "r"(a[2]), "r"(a[3]), "r"(b[0]), "r"(b[1]));
}

// Tile 128x128, K-tile 32, 256 threads (8 warps, each 64x32).
// TB=1: C = A[M,K] * B[N,K]^T (+bias);  TB=0: C = A[M,K] * B[K,N] (+bias)
template <int TB>
__global__ void __launch_bounds__(256) gemm_tf32(
    const float* __restrict__ A, const float* __restrict__ B,
    const float* __restrict__ bias, float* __restrict__ C,
    int N, int K, long long sA, long long sB, long long sC,
    int divA, int divB) {
    const int tid = threadIdx.x;
    int z = blockIdx.z;
    A += (long long)(z / divA) * sA + (long long)(blockIdx.y * 128) * K;
    if (TB) B += (long long)(z / divB) * sB + (long long)(blockIdx.x * 128) * K;
    else    B += (long long)(z / divB) * sB + blockIdx.x * 128;
    C += (long long)z * sC + (long long)(blockIdx.y * 128) * N + blockIdx.x * 128;

    __shared__ unsigned As[128 * 36];   // [m][k], pitch 36 -> conflict-free frags
    __shared__ unsigned Bs[128 * 36];   // TN: [n][k] pitch 36; NN: [k][n] pitch 132

    const int warp = tid >> 5, lane = tid & 31;
    const int wm = (warp & 1) * 64, wn = (warp >> 1) * 32;
    const int lq = lane >> 2, lr = lane & 3;

    const int sm = tid >> 3;         // 0..31 (row group, +32*i)
    const int sk = (tid & 7) * 4;    // 0..28
    const int bk = tid >> 5;         // 0..7 (NN k row, +8*i)
    const int bn = (tid & 31) * 4;   // 0..124

    float4 acc[4][4];
#pragma unroll
    for (int i = 0; i < 4; i++)
#pragma unroll
        for (int j = 0; j < 4; j++) acc[i][j] = make_float4(0.f, 0.f, 0.f, 0.f);

    float4 pa[4], pb[4];
#pragma unroll
    for (int i = 0; i < 4; i++)
        pa[i] = *reinterpret_cast<const float4*>(&A[(long long)(sm + 32 * i) * K + sk]);
    if (TB) {
#pragma unroll
        for (int i = 0; i < 4; i++)
            pb[i] = *reinterpret_cast<const float4*>(&B[(long long)(sm + 32 * i) * K + sk]);
    } else {
#pragma unroll
        for (int i = 0; i < 4; i++)
            pb[i] = *reinterpret_cast<const float4*>(&B[(long long)(bk + 8 * i) * N + bn]);
    }

    int k0 = 0;
    for (;;) {
#pragma unroll
        for (int i = 0; i < 4; i++) {
            uint4 u;
            u.x = f2tf(pa[i].x); u.y = f2tf(pa[i].y); u.z = f2tf(pa[i].z); u.w = f2tf(pa[i].w);
            *reinterpret_cast<uint4*>(&As[(sm + 32 * i) * 36 + sk]) = u;
        }
#pragma unroll
        for (int i = 0; i < 4; i++) {
            uint4 u;
            u.x = f2tf(pb[i].x); u.y = f2tf(pb[i].y); u.z = f2tf(pb[i].z); u.w = f2tf(pb[i].w);
            if (TB) *reinterpret_cast<uint4*>(&Bs[(sm + 32 * i) * 36 + sk]) = u;
            else    *reinterpret_cast<uint4*>(&Bs[(bk + 8 * i) * 132 + bn]) = u;
        }
        __syncthreads();

        int k1 = k0 + 32;
        if (k1 < K) {
#pragma unroll
            for (int i = 0; i < 4; i++)
                pa[i] = *reinterpret_cast<const float4*>(&A[(long long)(sm + 32 * i) * K + k1 + sk]);
            if (TB) {
#pragma unroll
                for (int i = 0; i < 4; i++)
                    pb[i] = *reinterpret_cast<const float4*>(&B[(long long)(sm + 32 * i) * K + k1 + sk]);
            } else {
#pragma unroll
                for (int i = 0; i < 4; i++)
                    pb[i] = *reinterpret_cast<const float4*>(&B[(long long)(k1 + bk + 8 * i) * N + bn]);
            }
        }

#pragma unroll
        for (int kk = 0; kk < 32; kk += 8) {
            unsigned a[4][4];
#pragma unroll
            for (int mt = 0; mt < 4; mt++) {
                int r = (wm + mt * 16 + lq) * 36 + kk + lr;
                a[mt][0] = As[r];
                a[mt][1] = As[r + 8 * 36];
                a[mt][2] = As[r + 4];
                a[mt][3] = As[r + 8 * 36 + 4];
            }
            unsigned b[4][2];
#pragma unroll
            for (int nt = 0; nt < 4; nt++) {
                if (TB) {
                    int r = (wn + nt * 8 + lq) * 36 + kk + lr;
                    b[nt][0] = Bs[r];
                    b[nt][1] = Bs[r + 4];
                } else {
                    int r = (kk + lr) * 132 + wn + nt * 8 + lq;
                    b[nt][0] = Bs[r];
                    b[nt][1] = Bs[r + 4 * 132];
                }
            }
#pragma unroll
            for (int mt = 0; mt < 4; mt++)
#pragma unroll
                for (int nt = 0; nt < 4; nt++) mma_tf32(acc[mt][nt], a[mt], b[nt]);
        }
        if (k1 >= K) break;
        __syncthreads();
        k0 = k1;
    }

#pragma unroll
    for (int nt = 0; nt < 4; nt++) {
        int col = wn + nt * 8 + 2 * lr;
        float bx = 0.f, by = 0.f;
        if (bias) {
            int cg = blockIdx.x * 128 + col;
            bx = bias[cg]; by = bias[cg + 1];
        }
#pragma unroll
        for (int mt = 0; mt < 4; mt++) {
            int row = wm + mt * 16 + lq;
            float4 v = acc[mt][nt];
            float2 v0 = make_float2(v.x + bx, v.y + by);
            float2 v1 = make_float2(v.z + bx, v.w + by);
            *reinterpret_cast<float2*>(&C[(long long)row * N + col]) = v0;
            *reinterpret_cast<float2*>(&C[(long long)(row + 8) * N + col]) = v1;
        }
    }
}

// ---------------- softmax: 1024 cols, block per row, regs-resident ----------------
__global__ void __launch_bounds__(256) softmax_block1024(const float* __restrict__ in,
                                                         float* __restrict__ out) {
    long long row = blockIdx.x;
    const float4* x = reinterpret_cast<const float4*>(in + row * 1024);
    float4* y = reinterpret_cast<float4*>(out + row * 1024);
    int tid = threadIdx.x, warp = tid >> 5, lane = tid & 31;
    __shared__ float redm[8], reds[8];
    float4 v = x[tid];
    float m = fmaxf(fmaxf(v.x, v.y), fmaxf(v.z, v.w));
#pragma unroll
    for (int off = 16; off; off >>= 1) m = fmaxf(m, __shfl_xor_sync(0xffffffffu, m, off));
    if (lane == 0) redm[warp] = m;
    __syncthreads();
    m = redm[0];
#pragma unroll
    for (int i = 1; i < 8; i++) m = fmaxf(m, redm[i]);
    v.x = expf(v.x - m); v.y = expf(v.y - m); v.z = expf(v.z - m); v.w = expf(v.w - m);
    float s = v.x + v.y + v.z + v.w;
#pragma unroll
    for (int off = 16; off; off >>= 1) s += __shfl_xor_sync(0xffffffffu, s, off);
    if (lane == 0) reds[warp] = s;
    __syncthreads();
    s = reds[0];
#pragma unroll
    for (int i = 1; i < 8; i++) s += reds[i];
    float inv = 1.f / s;
    v.x *= inv; v.y *= inv; v.z *= inv; v.w *= inv;
    y[tid] = v;
}

// ---------------- softmax: 128 cols, warp per row (8 rows per block) ----------------
__global__ void __launch_bounds__(256) softmax_warp128(const float* __restrict__ in,
                                                       float* __restrict__ out) {
    int warp = threadIdx.x >> 5, lane = threadIdx.x & 31;
    long long row = (long long)blockIdx.x * 8 + warp;
    const float4* x = reinterpret_cast<const float4*>(in + row * 128);
    float4* y = reinterpret_cast<float4*>(out + row * 128);
    float4 v = x[lane];
    float m = fmaxf(fmaxf(v.x, v.y), fmaxf(v.z, v.w));
#pragma unroll
    for (int off = 16; off; off >>= 1) m = fmaxf(m, __shfl_xor_sync(0xffffffffu, m, off));
    v.x = expf(v.x - m); v.y = expf(v.y - m); v.z = expf(v.z - m); v.w = expf(v.w - m);
    float s = v.x + v.y + v.z + v.w;
#pragma unroll
    for (int off = 16; off; off >>= 1) s += __shfl_xor_sync(0xffffffffu, s, off);
    float inv = 1.f / s;
    v.x *= inv; v.y *= inv; v.z *= inv; v.w *= inv;
    y[lane] = v;
}

// ---------------- column softmax of match over s, output transposed [bon][l][s] ----------------
__global__ void __launch_bounds__(128) softmax_cols_t() {
    int bon = blockIdx.y;
    int l = blockIdx.x * 4 + (threadIdx.x >> 5);
    int lane = threadIdx.x & 31;
    const float* base = g_match + (long long)bon * 256 * 128 + l;
    float v[8];
    float m = -1e30f;
#pragma unroll
    for (int i = 0; i < 8; i++) {
        v[i] = base[(lane + 32 * i) * 128];
        m = fmaxf(m, v[i]);
    }
#pragma unroll
    for (int off = 16; off; off >>= 1) m = fmaxf(m, __shfl_xor_sync(0xffffffffu, m, off));
    float sum = 0.f;
#pragma unroll
    for (int i = 0; i < 8; i++) { v[i] = expf(v[i] - m); sum += v[i]; }
#pragma unroll
    for (int off = 16; off; off >>= 1) sum += __shfl_xor_sync(0xffffffffu, sum, off);
    float inv = 1.f / sum;
    float* o = g_p2t + ((long long)bon * 128 + l) * 256;
#pragma unroll
    for (int i = 0; i < 8; i++) o[lane + 32 * i] = v[i] * inv;
}

// ---------------- acquire/relaxed flag ops ----------------
__device__ __forceinline__ unsigned ld_acq(const unsigned* p) {
    unsigned v;
    asm volatile("ld.global.acquire.gpu.u32 %0, [%1];" : "=r"(v) : "l"(p) : "memory");
    return v;
}
__device__ __forceinline__ void st_rlx(unsigned* p, unsigned v) {
    asm volatile("st.global.relaxed.gpu.u32 [%0], %1;" :: "l"(p), "r"(v) : "memory");
}

// ---------------- persistent fused GRU phase (flag-pipelined) ----------------
struct GG {
    const float* xg;    // [nseq][T][768]
    const float* whh;   // [768][256]
    const float* bhh;   // [768]
    float* h0;          // [nseq][256] (t even input)
    float* h1;
    float* ys;          // optional [nseq][T][256]
    float* hmax;        // optional [nseq][256]
    int T;
    int nsg;            // seq groups of 16
    int slotbase;       // flag slot base (one slot per sgrp)
};

#define WP 260  // weight row pitch (floats): 4-bank shift/row -> conflict-free 8-row frags
#define HP 264  // h row pitch (floats): 8-bank shift/row -> conflict-free 4-row frags

// packed fp32x2 FMA (sm_10x): acc{lo,hi} += a{lo,hi} * b{lo,hi}
#define FMA2(acc, a, b) \
    asm("fma.rn.f32x2 %0, %1, %2, %0;" : "+l"(acc) : "l"(a), "l"(b))
#define UNPK(lo, hi, v) \
    asm("mov.b64 {%0,%1}, %2;" : "=f"(lo), "=f"(hi) : "l"(v))

__device__ __forceinline__ float red1(unsigned long long a) {
    float lo, hi;
    UNPK(lo, hi, a);
    return lo + hi;
}

// block = 128 threads, tile = 16 seqs x 32 cols (one k/col chunk of 32).
// warp w owns cols chunk*32 + w*8 + [0,8); lane: c3 = lane&7 (col), sq = lane>>3;
// thread computes 4 cells: (seqs sq+4j, its col). k loop pipelined over the 8
// chunks in rotated order (own chunk first), gated by per-chunk step flags.
__global__ void __launch_bounds__(128) gru_phase(GG ga, GG gb) {
    extern __shared__ float smx[];
    float* ws = smx;               // 96 x WP
    float* hs = smx + 96 * WP;     // 16 x HP

    GG g;
    int sgrp, mychunk;
    {
        int b = blockIdx.x;
        int blocks0 = ga.nsg * 8;
        if (b < blocks0) { g = ga; sgrp = b >> 3; mychunk = b & 7; }
        else { g = gb; int bb = b - blocks0; sgrp = bb >> 3; mychunk = bb & 7; }
    }
    const int tid = threadIdx.x;
    const int warp = tid >> 5, lane = tid & 31;
    const int c3 = lane & 7;        // col within warp's 8
    const int sq = lane >> 3;       // 0..3 seq base
    const int widx = warp * 8 + c3; // col within chunk, 0..31
    const int col = mychunk * 32 + widx;
    unsigned* flags = &g_flag[(g.slotbase + sgrp) * 8 * 32];

    // load weight slice: ws row r = gate*32 + j holds whh[gate*256 + col0 + j][:]
    for (int i = tid; i < 96 * 64; i += 128) {
        int r = i >> 6, q = i & 63;
        float4 v = __ldg(reinterpret_cast<const float4*>(
            &g.whh[(long long)((r >> 5) * 256 + mychunk * 32 + (r & 31)) * 256 + q * 4]));
        *reinterpret_cast<float4*>(&ws[r * WP + q * 4]) = v;
    }
    const float br = g.bhh[col], bz = g.bhh[256 + col], bn = g.bhh[512 + col];
    float mx[4] = {-1e30f, -1e30f, -1e30f, -1e30f};

    const ulonglong2* wR = reinterpret_cast<const ulonglong2*>(&ws[(0 + widx) * WP]);
    const ulonglong2* wZ = reinterpret_cast<const ulonglong2*>(&ws[(32 + widx) * WP]);
    const ulonglong2* wN = reinterpret_cast<const ulonglong2*>(&ws[(64 + widx) * WP]);
    const ulonglong2* hrow[4];
#pragma unroll
    for (int j = 0; j < 4; j++)
        hrow[j] = reinterpret_cast<const ulonglong2*>(&hs[(sq + 4 * j) * HP]);
    // HP/4 = 66 ulonglong2 per row; WP/4 = 65 per row
    const int stage_seq = tid >> 3, stage_q = tid & 7;

    const int T = g.T;
    __syncthreads();  // ws ready

    for (int t = 0; t < T; t++) {
        const float* hin = (t & 1) ? g.h1 : g.h0;
        float* hout = (t & 1) ? g.h0 : g.h1;
        const float* tilebase = hin + (long long)sgrp * 16 * 256;

        // xg prefetch (independent of other blocks)
        float xr[4], xz[4], xn[4];
#pragma unroll
        for (int j = 0; j < 4; j++) {
            long long base = ((long long)(sgrp * 16 + sq + 4 * j) * T + t) * 768;
            xr[j] = __ldg(&g.xg[base + col]);
            xz[j] = __ldg(&g.xg[base + 256 + col]);
            xn[j] = __ldg(&g.xg[base + 512 + col]);
        }

        unsigned long long aR[4], aZ[4], aN[4];
#pragma unroll
        for (int j = 0; j < 4; j++) { aR[j] = 0ull; aZ[j] = 0ull; aN[j] = 0ull; }

        // own chunk needs no wait (we produced it last step)
        float4 v = __ldcg(reinterpret_cast<const float4*>(tilebase) +
                          (stage_seq * 64 + mychunk * 8 + stage_q));

        for (int j2 = 0; j2 < 8; j2++) {
            int c = (mychunk + j2) & 7;
            *reinterpret_cast<float4*>(&hs[stage_seq * HP + c * 32 + stage_q * 4]) = v;
            if (j2 < 7) {
                int cn = (mychunk + j2 + 1) & 7;
                while (ld_acq(&flags[cn * 32]) < (unsigned)t) {}
                v = __ldcg(reinterpret_cast<const float4*>(tilebase) +
                           (stage_seq * 64 + cn * 8 + stage_q));
            }
            __syncthreads();
            int q0 = c * 8;
#pragma unroll
            for (int q = 0; q < 8; q++) {
                int qw = (q0 + q);          // 16B index within 256-float k
                ulonglong2 wr_ = wR[qw], wz_ = wZ[qw], wn_ = wN[qw];
#pragma unroll
                for (int j = 0; j < 4; j++) {
                    ulonglong2 h = hrow[j][qw + (sq + 4 * j) * 0 + 0];
                    // note: hrow already offset by row; qw indexes within row of HP/4=66
                    FMA2(aR[j], wr_.x, h.x); FMA2(aR[j], wr_.y, h.y);
                    FMA2(aZ[j], wz_.x, h.x); FMA2(aZ[j], wz_.y, h.y);
                    FMA2(aN[j], wn_.x, h.x); FMA2(aN[j], wn_.y, h.y);
                }
            }
        }

        // gate math + stores (4 seqs, 1 col per thread)
#pragma unroll
        for (int j = 0; j < 4; j++) {
            int sl = sq + 4 * j;
            long long seq = sgrp * 16 + sl;
            float hr = red1(aR[j]) + br;
            float hz = red1(aZ[j]) + bz;
            float hn = red1(aN[j]) + bn;
            float r = 1.f / (1.f + expf(-(xr[j] + hr)));
            float z = 1.f / (1.f + expf(-(xz[j] + hz)));
            float n = tanhf(xn[j] + r * hn);
            float hold = hs[sl * HP + col];
            float h = (1.f - z) * n + z * hold;
            hout[seq * 256 + col] = h;
            if (g.ys) g.ys[(seq * T + t) * 256 + col] = h;
            mx[j] = fmaxf(mx[j], h);
        }

        if (t + 1 < T) {
            __threadfence();
            __syncthreads();
            if (tid == 0) st_rlx(&flags[mychunk * 32], (unsigned)(t + 1));
        }
    }
    if (g.hmax) {
#pragma unroll
        for (int j = 0; j < 4; j++) {
            long long seq = sgrp * 16 + sq + 4 * j;
            g.hmax[seq * 256 + col] = mx[j];
        }
    }
}

// ---------------- final: coef gate, feat, output head, softmax over options ----------------
__global__ void __launch_bounds__(512) final_kernel(
    const float* __restrict__ gate_w, const float* __restrict__ gate_b,
    const float* __restrict__ out_w, const float* __restrict__ out_b,
    float* __restrict__ out) {
    __shared__ float coef[128];
    __shared__ float logits[16];
    int tid = threadIdx.x, w = tid >> 5, lane = tid & 31;
    for (int bon = w; bon < 128; bon += 16) {
        float s = 0.f;
        for (int d = lane; d < 512; d += 32) {
            float rv = (d < 256) ? g_srmax[bon * 256 + d] : g_drmax[bon * 256 + d - 256];
            s += rv * gate_w[d];
        }
#pragma unroll
        for (int off = 16; off; off >>= 1) s += __shfl_xor_sync(0xffffffffu, s, off);
        if (lane == 0) coef[bon] = s + gate_b[0];
    }
    __syncthreads();
    {
        int bo = w;
        float acc = 0.f;
        for (int d = lane; d < 1024; d += 32) {
            float v;
            if (d < 512) {
                float mxv = -1e30f;
#pragma unroll
                for (int n = 0; n < 8; n++) {
                    int bon = bo * 8 + n;
                    float rv = (d < 256) ? g_srmax[bon * 256 + d] : g_drmax[bon * 256 + d - 256];
                    mxv = fmaxf(mxv, coef[bon] * rv);
                }
                v = mxv;
            } else {
                int dd = d - 512;
                float smv = 0.f;
#pragma unroll
                for (int n = 0; n < 8; n++) {
                    int bon = bo * 8 + n;
                    float rv = (dd < 256) ? g_srmax[bon * 256 + dd] : g_drmax[bon * 256 + dd - 256];
                    smv += coef[bon] * rv;
                }
                v = smv * 0.125f;
            }
            acc += v * out_w[d];
        }
#pragma unroll
        for (int off = 16; off; off >>= 1) acc += __shfl_xor_sync(0xffffffffu, acc, off);
        if (lane == 0) logits[bo] = acc + out_b[0];
    }
    __syncthreads();
    if (tid < 4) {
        int b = tid;
        float m = -1e30f;
        for (int o = 0; o < 4; o++) m = fmaxf(m, logits[b * 4 + o]);
        float e[4], s = 0.f;
        for (int o = 0; o < 4; o++) { e[o] = expf(logits[b * 4 + o] - m); s += e[o]; }
        for (int o = 0; o < 4; o++) out[b * 4 + o] = e[o] / s;
    }
}

// ---------------- host orchestration ----------------
#define SYM(p, s) do { void* _t = nullptr; cudaGetSymbolAddress(&_t, s); p = (float*)_t; } while (0)

static const int GRU_SMEM = (96 * WP + 16 * HP) * 4;  // 116,736 B

extern "C" void kernel_launch(void* const* d_in, const int* in_sizes, int n_in,
                              void* d_out, int out_size) {
    const float* statement = (const float*)d_in[0];
    const float* answer    = (const float*)d_in[1];
    const float* refs      = (const float*)d_in[2];
    const float* ctx_wih   = (const float*)d_in[3];
    const float* ctx_whh   = (const float*)d_in[4];
    const float* ctx_bih   = (const float*)d_in[5];
    const float* ctx_bhh   = (const float*)d_in[6];
    const float* sr_wih    = (const float*)d_in[7];
    const float* sr_whh    = (const float*)d_in[8];
    const float* sr_bih    = (const float*)d_in[9];
    const float* sr_bhh    = (const float*)d_in[10];
    const float* dr_wih    = (const float*)d_in[11];
    const float* dr_whh    = (const float*)d_in[12];
    const float* dr_bih    = (const float*)d_in[13];
    const float* dr_bhh    = (const float*)d_in[14];
    const float* gate_w    = (const float*)d_in[15];
    const float* gate_b    = (const float*)d_in[16];
    const float* out_w     = (const float*)d_in[17];
    const float* out_b     = (const float*)d_in[18];
    float* out = (float*)d_out;

    float *stmt_in, *xg_stmt, *stmt_h, *xg_docs, *docs_h;
    float *hs0, *hs1, *hd0, *hd1;
    float *matchb, *p1, *p2t, *read_sum, *doc_read, *dri, *mmb, *att;
    float *xg_sr, *xg_dr, *hsr0, *hsr1, *hdr0, *hdr1, *srmax, *drmax;
    SYM(stmt_in, g_stmt_in); SYM(xg_stmt, g_xg_stmt); SYM(stmt_h, g_stmt_h);
    SYM(xg_docs, g_xg_docs); SYM(docs_h, g_docs_h);
    SYM(hs0, g_hs0); SYM(hs1, g_hs1); SYM(hd0, g_hd0); SYM(hd1, g_hd1);
    SYM(matchb, g_match); SYM(p1, g_p1); SYM(p2t, g_p2t);
    SYM(read_sum, g_read_sum); SYM(doc_read, g_doc_read); SYM(dri, g_dri);
    SYM(mmb, g_mm); SYM(att, g_att);
    SYM(xg_sr, g_xg_sr); SYM(xg_dr, g_xg_dr);
    SYM(hsr0, g_hsr0); SYM(hsr1, g_hsr1); SYM(hdr0, g_hdr0); SYM(hdr1, g_hdr1);
    SYM(srmax, g_srmax); SYM(drmax, g_drmax);

    cudaFuncSetAttribute(gru_phase, cudaFuncAttributeMaxDynamicSharedMemorySize, GRU_SMEM);

    init_state<<<128, 256>>>();
    concat_stmt<<<4096, 256>>>(statement, answer);

    // input projections for ctx GRU (TN: W is [768, in])
    gemm_tf32<1><<<dim3(6, 32, 1), 256>>>(stmt_in, ctx_wih, ctx_bih, xg_stmt,
                                          768, 256, 0, 0, 0, 1, 1);
    gemm_tf32<1><<<dim3(6, 128, 1), 256>>>(refs, ctx_wih, ctx_bih, xg_docs,
                                           768, 256, 0, 0, 0, 1, 1);

    // phase A: ctx GRU — stmt (16 seqs, T=256) || docs (128 seqs, T=128)
    {
        GG gs; gs.xg = xg_stmt; gs.whh = ctx_whh; gs.bhh = ctx_bhh;
        gs.h0 = hs0; gs.h1 = hs1; gs.ys = stmt_h; gs.hmax = nullptr;
        gs.T = 256; gs.nsg = 1; gs.slotbase = 0;
        GG gd; gd.xg = xg_docs; gd.whh = ctx_whh; gd.bhh = ctx_bhh;
        gd.h0 = hd0; gd.h1 = hd1; gd.ys = docs_h; gd.hmax = nullptr;
        gd.T = 128; gd.nsg = 8; gd.slotbase = 16;
        gru_phase<<<72, 128, GRU_SMEM>>>(gs, gd);  // 72 blocks, 1/SM
    }

    // match[bon][s][l] = stmt[bo,s,:] . docs[bon,l,:]
    gemm_tf32<1><<<dim3(1, 2, 128), 256>>>(stmt_h, docs_h, nullptr, matchb,
                                           128, 256, 65536, 32768, 32768, 8, 1);
    softmax_warp128<<<4096, 256>>>(matchb, p1);
    softmax_cols_t<<<dim3(32, 128), 128>>>();
    // read_sum = p1 @ docs ; doc_read = p2t @ stmt
    gemm_tf32<0><<<dim3(2, 2, 128), 256>>>(p1, docs_h, nullptr, read_sum,
                                           256, 128, 32768, 32768, 65536, 1, 1);
    gemm_tf32<0><<<dim3(2, 1, 128), 256>>>(p2t, stmt_h, nullptr, doc_read,
                                           256, 256, 32768, 65536, 32768, 1, 8);
    concat_dri<<<4096, 256>>>();

    // doc-doc cross attention per bo: mm = dri @ dri^T ; softmax ; att = p3 @ dri
    gemm_tf32<1><<<dim3(8, 8, 16), 256>>>(dri, dri, nullptr, mmb,
                                          1024, 512, 524288, 524288, 1048576, 1, 1);
    softmax_block1024<<<16384, 256>>>(mmb, mmb);
    gemm_tf32<0><<<dim3(4, 8, 16), 256>>>(mmb, dri, nullptr, att,
                                          512, 1024, 1048576, 524288, 524288, 1, 1);

    // input projections for reasoning GRUs
    gemm_tf32<1><<<dim3(6, 256, 1), 256>>>(read_sum, sr_wih, sr_bih, xg_sr,
                                           768, 256, 0, 0, 0, 1, 1);
    gemm_tf32<1><<<dim3(6, 128, 1), 256>>>(att, dr_wih, dr_bih, xg_dr,
                                           768, 512, 0, 0, 0, 1, 1);

    // phase C: reasoning GRUs — sr (128 seqs, T=256) || dr (128 seqs, T=128)
    {
        GG ga; ga.xg = xg_sr; ga.whh = sr_whh; ga.bhh = sr_bhh;
        ga.h0 = hsr0; ga.h1 = hsr1; ga.ys = nullptr; ga.hmax = srmax;
        ga.T = 256; ga.nsg = 8; ga.slotbase = 32;
        GG gb; gb.xg = xg_dr; gb.whh = dr_whh; gb.bhh = dr_bhh;
        gb.h0 = hdr0; gb.h1 = hdr1; gb.ys = nullptr; gb.hmax = drmax;
        gb.T = 128; gb.nsg = 8; gb.slotbase = 48;
        gru_phase<<<128, 128, GRU_SMEM>>>(ga, gb);  // 128 blocks, 1/SM
    }

    final_kernel<<<1, 512>>>(gate_w, gate_b, out_w, out_b, out);
}

// round 9
// speedup vs baseline: 1.0810x; 1.0810x over previous
#include <cuda_runtime.h>
#include <math.h>

// Problem dims: B=4 O=4 L=128 N=8 V=256 H=256, Ls=2L=256, BO=16, BON=128, NL=1024

// ---------------- scratch (device globals; no allocation allowed) ----------------
__device__ float g_stmt_in[16 * 256 * 256];
__device__ float g_xg_stmt[16 * 256 * 768];
__device__ float g_stmt_h[16 * 256 * 256];
__device__ float g_xg_docs[128 * 128 * 768];
__device__ float g_docs_h[128 * 128 * 256];
__device__ float g_hs0[16 * 256], g_hs1[16 * 256];
__device__ float g_hd0[128 * 256], g_hd1[128 * 256];
__device__ float g_match[128 * 256 * 128];
__device__ float g_p1[128 * 256 * 128];
__device__ float g_p2t[128 * 128 * 256];
__device__ float g_read_sum[128 * 256 * 256];
__device__ float g_doc_read[128 * 128 * 256];
__device__ float g_dri[128 * 128 * 512];
__device__ float g_mm[16 * 1024 * 1024];
__device__ float g_att[128 * 128 * 512];
__device__ float g_xg_sr[128 * 256 * 768];
__device__ float g_xg_dr[128 * 128 * 768];
__device__ float g_hsr0[128 * 256], g_hsr1[128 * 256];
__device__ float g_hdr0[128 * 256], g_hdr1[128 * 256];
__device__ float g_srmax[128 * 256], g_drmax[128 * 256];

// per-(slot, chunk) monotonic step flags: 64 slots x 8 chunks, 128B stride
__device__ unsigned g_flag[64 * 8 * 32];

// ---------------- init ----------------
__global__ void init_state() {
    int i = blockIdx.x * 256 + threadIdx.x;  // 32768 threads
    if (i < 64 * 8 * 32) g_flag[i] = 0u;
    if (i < 16 * 256) { g_hs0[i] = 0.f; g_hs1[i] = 0.f; }
    if (i < 128 * 256) {
        g_hd0[i] = 0.f;  g_hd1[i] = 0.f;
        g_hsr0[i] = 0.f; g_hsr1[i] = 0.f;
        g_hdr0[i] = 0.f; g_hdr1[i] = 0.f;
    }
}

// ---------------- build stmt = cat(question, answer) ----------------
__global__ void concat_stmt(const float* __restrict__ statement,
                            const float* __restrict__ answer) {
    int idx = blockIdx.x * 256 + threadIdx.x;  // 1048576
    int v = idx & 255;
    int s = (idx >> 8) & 255;
    int bo = idx >> 16;
    int b = bo >> 2;
    float val;
    if (s < 128) val = statement[(b * 128 + s) * 256 + v];
    else         val = answer[(bo * 128 + (s - 128)) * 256 + v];
    g_stmt_in[idx] = val;
}

// ---------------- dri = cat(docs, doc_read) ----------------
__global__ void concat_dri() {
    for (int idx = blockIdx.x * blockDim.x + threadIdx.x; idx < 128 * 128 * 512;
         idx += gridDim.x * blockDim.x) {
        int h = idx & 511;
        int rest = idx >> 9;
        g_dri[idx] = (h < 256) ? g_docs_h[rest * 256 + h]
                               : g_doc_read[rest * 256 + (h - 256)];
    }
}

// ---------------- tf32 tensor-core GEMM ----------------
__device__ __forceinline__ unsigned f2tf(float x) {
    unsigned r;
    asm("cvt.rna.tf32.f32 %0, %1;" : "=r"(r) : "f"(x));
    return r;
}

__device__ __forceinline__ void mma_tf32(float4& d, const unsigned* a, const unsigned* b) {
    asm volatile(
        "mma.sync.aligned.m16n8k8.row.col.f32.tf32.tf32.f32 "
        "{%0,%1,%2,%3}, {%4,%5,%6,%7}, {%8,%9}, {%0,%1,%2,%3};"
        : "+f"(d.x), "+f"(d.y), "+f"(d.z), "+f"(d.w)
        : "r"(a[0]), "r"(a[1]), "r"(a[2]), "r"(a[3]), "r"(b[0]), "r"(b[1]));
}

// Tile 128x128, K-tile 32, 256 threads (8 warps, each 64x32).
// TB=1: C = A[M,K] * B[N,K]^T (+bias);  TB=0: C = A[M,K] * B[K,N] (+bias)
template <int TB>
__global__ void __launch_bounds__(256) gemm_tf32(
    const float* __restrict__ A, const float* __restrict__ B,
    const float* __restrict__ bias, float* __restrict__ C,
    int N, int K, long long sA, long long sB, long long sC,
    int divA, int divB) {
    const int tid = threadIdx.x;
    int z = blockIdx.z;
    A += (long long)(z / divA) * sA + (long long)(blockIdx.y * 128) * K;
    if (TB) B += (long long)(z / divB) * sB + (long long)(blockIdx.x * 128) * K;
    else    B += (long long)(z / divB) * sB + blockIdx.x * 128;
    C += (long long)z * sC + (long long)(blockIdx.y * 128) * N + blockIdx.x * 128;

    __shared__ unsigned As[128 * 36];   // [m][k], pitch 36 -> conflict-free frags
    __shared__ unsigned Bs[128 * 36];   // TN: [n][k] pitch 36; NN: [k][n] pitch 132

    const int warp = tid >> 5, lane = tid & 31;
    const int wm = (warp & 1) * 64, wn = (warp >> 1) * 32;
    const int lq = lane >> 2, lr = lane & 3;

    const int sm = tid >> 3;         // 0..31 (row group, +32*i)
    const int sk = (tid & 7) * 4;    // 0..28
    const int bk = tid >> 5;         // 0..7 (NN k row, +8*i)
    const int bn = (tid & 31) * 4;   // 0..124

    float4 acc[4][4];
#pragma unroll
    for (int i = 0; i < 4; i++)
#pragma unroll
        for (int j = 0; j < 4; j++) acc[i][j] = make_float4(0.f, 0.f, 0.f, 0.f);

    float4 pa[4], pb[4];
#pragma unroll
    for (int i = 0; i < 4; i++)
        pa[i] = *reinterpret_cast<const float4*>(&A[(long long)(sm + 32 * i) * K + sk]);
    if (TB) {
#pragma unroll
        for (int i = 0; i < 4; i++)
            pb[i] = *reinterpret_cast<const float4*>(&B[(long long)(sm + 32 * i) * K + sk]);
    } else {
#pragma unroll
        for (int i = 0; i < 4; i++)
            pb[i] = *reinterpret_cast<const float4*>(&B[(long long)(bk + 8 * i) * N + bn]);
    }

    int k0 = 0;
    for (;;) {
#pragma unroll
        for (int i = 0; i < 4; i++) {
            uint4 u;
            u.x = f2tf(pa[i].x); u.y = f2tf(pa[i].y); u.z = f2tf(pa[i].z); u.w = f2tf(pa[i].w);
            *reinterpret_cast<uint4*>(&As[(sm + 32 * i) * 36 + sk]) = u;
        }
#pragma unroll
        for (int i = 0; i < 4; i++) {
            uint4 u;
            u.x = f2tf(pb[i].x); u.y = f2tf(pb[i].y); u.z = f2tf(pb[i].z); u.w = f2tf(pb[i].w);
            if (TB) *reinterpret_cast<uint4*>(&Bs[(sm + 32 * i) * 36 + sk]) = u;
            else    *reinterpret_cast<uint4*>(&Bs[(bk + 8 * i) * 132 + bn]) = u;
        }
        __syncthreads();

        int k1 = k0 + 32;
        if (k1 < K) {
#pragma unroll
            for (int i = 0; i < 4; i++)
                pa[i] = *reinterpret_cast<const float4*>(&A[(long long)(sm + 32 * i) * K + k1 + sk]);
            if (TB) {
#pragma unroll
                for (int i = 0; i < 4; i++)
                    pb[i] = *reinterpret_cast<const float4*>(&B[(long long)(sm + 32 * i) * K + k1 + sk]);
            } else {
#pragma unroll
                for (int i = 0; i < 4; i++)
                    pb[i] = *reinterpret_cast<const float4*>(&B[(long long)(k1 + bk + 8 * i) * N + bn]);
            }
        }

#pragma unroll
        for (int kk = 0; kk < 32; kk += 8) {
            unsigned a[4][4];
#pragma unroll
            for (int mt = 0; mt < 4; mt++) {
                int r = (wm + mt * 16 + lq) * 36 + kk + lr;
                a[mt][0] = As[r];
                a[mt][1] = As[r + 8 * 36];
                a[mt][2] = As[r + 4];
                a[mt][3] = As[r + 8 * 36 + 4];
            }
            unsigned b[4][2];
#pragma unroll
            for (int nt = 0; nt < 4; nt++) {
                if (TB) {
                    int r = (wn + nt * 8 + lq) * 36 + kk + lr;
                    b[nt][0] = Bs[r];
                    b[nt][1] = Bs[r + 4];
                } else {
                    int r = (kk + lr) * 132 + wn + nt * 8 + lq;
                    b[nt][0] = Bs[r];
                    b[nt][1] = Bs[r + 4 * 132];
                }
            }
#pragma unroll
            for (int mt = 0; mt < 4; mt++)
#pragma unroll
                for (int nt = 0; nt < 4; nt++) mma_tf32(acc[mt][nt], a[mt], b[nt]);
        }
        if (k1 >= K) break;
        __syncthreads();
        k0 = k1;
    }

#pragma unroll
    for (int nt = 0; nt < 4; nt++) {
        int col = wn + nt * 8 + 2 * lr;
        float bx = 0.f, by = 0.f;
        if (bias) {
            int cg = blockIdx.x * 128 + col;
            bx = bias[cg]; by = bias[cg + 1];
        }
#pragma unroll
        for (int mt = 0; mt < 4; mt++) {
            int row = wm + mt * 16 + lq;
            float4 v = acc[mt][nt];
            float2 v0 = make_float2(v.x + bx, v.y + by);
            float2 v1 = make_float2(v.z + bx, v.w + by);
            *reinterpret_cast<float2*>(&C[(long long)row * N + col]) = v0;
            *reinterpret_cast<float2*>(&C[(long long)(row + 8) * N + col]) = v1;
        }
    }
}

// ---------------- softmax: 1024 cols, block per row, regs-resident ----------------
__global__ void __launch_bounds__(256) softmax_block1024(const float* __restrict__ in,
                                                         float* __restrict__ out) {
    long long row = blockIdx.x;
    const float4* x = reinterpret_cast<const float4*>(in + row * 1024);
    float4* y = reinterpret_cast<float4*>(out + row * 1024);
    int tid = threadIdx.x, warp = tid >> 5, lane = tid & 31;
    __shared__ float redm[8], reds[8];
    float4 v = x[tid];
    float m = fmaxf(fmaxf(v.x, v.y), fmaxf(v.z, v.w));
#pragma unroll
    for (int off = 16; off; off >>= 1) m = fmaxf(m, __shfl_xor_sync(0xffffffffu, m, off));
    if (lane == 0) redm[warp] = m;
    __syncthreads();
    m = redm[0];
#pragma unroll
    for (int i = 1; i < 8; i++) m = fmaxf(m, redm[i]);
    v.x = expf(v.x - m); v.y = expf(v.y - m); v.z = expf(v.z - m); v.w = expf(v.w - m);
    float s = v.x + v.y + v.z + v.w;
#pragma unroll
    for (int off = 16; off; off >>= 1) s += __shfl_xor_sync(0xffffffffu, s, off);
    if (lane == 0) reds[warp] = s;
    __syncthreads();
    s = reds[0];
#pragma unroll
    for (int i = 1; i < 8; i++) s += reds[i];
    float inv = 1.f / s;
    v.x *= inv; v.y *= inv; v.z *= inv; v.w *= inv;
    y[tid] = v;
}

// ---------------- softmax: 128 cols, warp per row (8 rows per block) ----------------
__global__ void __launch_bounds__(256) softmax_warp128(const float* __restrict__ in,
                                                       float* __restrict__ out) {
    int warp = threadIdx.x >> 5, lane = threadIdx.x & 31;
    long long row = (long long)blockIdx.x * 8 + warp;
    const float4* x = reinterpret_cast<const float4*>(in + row * 128);
    float4* y = reinterpret_cast<float4*>(out + row * 128);
    float4 v = x[lane];
    float m = fmaxf(fmaxf(v.x, v.y), fmaxf(v.z, v.w));
#pragma unroll
    for (int off = 16; off; off >>= 1) m = fmaxf(m, __shfl_xor_sync(0xffffffffu, m, off));
    v.x = expf(v.x - m); v.y = expf(v.y - m); v.z = expf(v.z - m); v.w = expf(v.w - m);
    float s = v.x + v.y + v.z + v.w;
#pragma unroll
    for (int off = 16; off; off >>= 1) s += __shfl_xor_sync(0xffffffffu, s, off);
    float inv = 1.f / s;
    v.x *= inv; v.y *= inv; v.z *= inv; v.w *= inv;
    y[lane] = v;
}

// ---------------- column softmax of match over s, output transposed [bon][l][s] ----------------
__global__ void __launch_bounds__(128) softmax_cols_t() {
    int bon = blockIdx.y;
    int l = blockIdx.x * 4 + (threadIdx.x >> 5);
    int lane = threadIdx.x & 31;
    const float* base = g_match + (long long)bon * 256 * 128 + l;
    float v[8];
    float m = -1e30f;
#pragma unroll
    for (int i = 0; i < 8; i++) {
        v[i] = base[(lane + 32 * i) * 128];
        m = fmaxf(m, v[i]);
    }
#pragma unroll
    for (int off = 16; off; off >>= 1) m = fmaxf(m, __shfl_xor_sync(0xffffffffu, m, off));
    float sum = 0.f;
#pragma unroll
    for (int i = 0; i < 8; i++) { v[i] = expf(v[i] - m); sum += v[i]; }
#pragma unroll
    for (int off = 16; off; off >>= 1) sum += __shfl_xor_sync(0xffffffffu, sum, off);
    float inv = 1.f / sum;
    float* o = g_p2t + ((long long)bon * 128 + l) * 256;
#pragma unroll
    for (int i = 0; i < 8; i++) o[lane + 32 * i] = v[i] * inv;
}

// ---------------- acquire/relaxed flag ops ----------------
__device__ __forceinline__ unsigned ld_acq(const unsigned* p) {
    unsigned v;
    asm volatile("ld.global.acquire.gpu.u32 %0, [%1];" : "=r"(v) : "l"(p) : "memory");
    return v;
}
__device__ __forceinline__ void st_rlx(unsigned* p, unsigned v) {
    asm volatile("st.global.relaxed.gpu.u32 [%0], %1;" :: "l"(p), "r"(v) : "memory");
}

// ---------------- persistent fused GRU phase ----------------
struct GG {
    const float* xg;    // [nseq][T][768]
    const float* whh;   // [768][256]
    const float* bhh;   // [768]
    float* h0;          // [nseq][256] (t even input)
    float* h1;
    float* ys;          // optional [nseq][T][256]
    float* hmax;        // optional [nseq][256]
    int T;
    int nsg;            // seq groups of 16
    int slotbase;       // flag slot base (one slot per sgrp)
};

#define WP 260  // padded weight row pitch (floats)

// packed fp32x2 FMA (sm_10x): acc{lo,hi} += a{lo,hi} * b{lo,hi}
#define FMA2(acc, a, b) \
    asm("fma.rn.f32x2 %0, %1, %2, %0;" : "+l"(acc) : "l"(a), "l"(b))
#define UNPK(lo, hi, v) \
    asm("mov.b64 {%0,%1}, %2;" : "=f"(lo), "=f"(hi) : "l"(v))

__device__ __forceinline__ float red2(unsigned long long a, unsigned long long b) {
    float l0, h0, l1, h1;
    UNPK(l0, h0, a); UNPK(l1, h1, b);
    return (l0 + h0) + (l1 + h1);
}

// distributed 8-block barrier: each block publishes a monotonic step counter on
// its own flag line; threads 0-7 poll the 8 flags in parallel. No atomics.
__device__ __forceinline__ void group_barrier(unsigned* flags, int mychunk, unsigned tnext) {
    __syncthreads();  // all threads' h stores issued
    int tid = threadIdx.x;
    if (tid < 8) {
        if (tid == 0) {
            __threadfence();                       // order h stores before flag
            st_rlx(&flags[mychunk * 32], tnext);   // publish own step
        }
        while (ld_acq(&flags[tid * 32]) < tnext) {}  // 8 parallel polls
    }
    __syncthreads();
}

// block = 128 threads, tile = 16 seqs x 32 cols. grid = (ga.nsg + gb.nsg) * 8 blocks.
// Blocks of the same sgrp sync among themselves only and exit at T.
__global__ void __launch_bounds__(128) gru_phase(GG ga, GG gb) {
    extern __shared__ float sm[];
    float* ws = sm;               // 96 x WP
    float* hs = sm + 96 * WP;     // 16 x 256

    GG g;
    int sgrp, mychunk;
    {
        int b = blockIdx.x;
        int blocks0 = ga.nsg * 8;
        if (b < blocks0) { g = ga; sgrp = b >> 3; mychunk = b & 7; }
        else { g = gb; int bb = b - blocks0; sgrp = bb >> 3; mychunk = bb & 7; }
    }
    const int colbase = mychunk * 32;
    unsigned* flags = &g_flag[(g.slotbase + sgrp) * 8 * 32];
    const int tid = threadIdx.x;
    const int ci = tid & 15;
    const int sj = tid >> 4;  // 0..7

    // load weight slice: rows {gate*256 + colbase + j}, j in [0,32), all 256 k
    for (int i = tid; i < 96 * 64; i += 128) {
        int r = i >> 6, q = i & 63;
        float4 v = __ldg(reinterpret_cast<const float4*>(
            &g.whh[(long long)((r >> 5) * 256 + colbase + (r & 31)) * 256 + q * 4]));
        *reinterpret_cast<float4*>(&ws[r * WP + q * 4]) = v;
    }
    const int c0 = colbase + ci, c1 = c0 + 16;
    const float br0 = g.bhh[c0], bz0 = g.bhh[256 + c0], bn0 = g.bhh[512 + c0];
    const float br1 = g.bhh[c1], bz1 = g.bhh[256 + c1], bn1 = g.bhh[512 + c1];
    float mx00 = -1e30f, mx01 = -1e30f, mx10 = -1e30f, mx11 = -1e30f;

    // weight rows as packed-pair pointers: [R c0][R c1][Z c0][Z c1][N c0][N c1]
    const ulonglong2* wp[6];
    wp[0] = reinterpret_cast<const ulonglong2*>(&ws[(0 * 32 + ci) * WP]);
    wp[1] = reinterpret_cast<const ulonglong2*>(&ws[(0 * 32 + ci + 16) * WP]);
    wp[2] = reinterpret_cast<const ulonglong2*>(&ws[(1 * 32 + ci) * WP]);
    wp[3] = reinterpret_cast<const ulonglong2*>(&ws[(1 * 32 + ci + 16) * WP]);
    wp[4] = reinterpret_cast<const ulonglong2*>(&ws[(2 * 32 + ci) * WP]);
    wp[5] = reinterpret_cast<const ulonglong2*>(&ws[(2 * 32 + ci + 16) * WP]);
    const ulonglong2* h0p = reinterpret_cast<const ulonglong2*>(&hs[sj * 256]);
    const ulonglong2* h1p = reinterpret_cast<const ulonglong2*>(&hs[(sj + 8) * 256]);

    const int T = g.T;
    for (int t = 0; t < T; t++) {
        const float* hin = (t & 1) ? g.h1 : g.h0;
        float* hout = (t & 1) ? g.h0 : g.h1;
        const float* tilebase = hin + (long long)sgrp * 16 * 256;
        // stage h tile [16][256] (L2-only loads: written by other SMs last step)
#pragma unroll
        for (int i = 0; i < 8; i++) {
            int idx = tid + i * 128;  // 0..1023 float4
            float4 v = __ldcg(reinterpret_cast<const float4*>(tilebase) + idx);
            *reinterpret_cast<float4*>(&hs[idx * 4]) = v;
        }
        // prefetch xg for this thread's 4 cells
        const long long base0 = ((long long)(sgrp * 16 + sj) * T + t) * 768;
        const long long base1 = ((long long)(sgrp * 16 + sj + 8) * T + t) * 768;
        float xr00 = __ldg(&g.xg[base0 + c0]);
        float xz00 = __ldg(&g.xg[base0 + 256 + c0]);
        float xn00 = __ldg(&g.xg[base0 + 512 + c0]);
        float xr01 = __ldg(&g.xg[base0 + c1]);
        float xz01 = __ldg(&g.xg[base0 + 256 + c1]);
        float xn01 = __ldg(&g.xg[base0 + 512 + c1]);
        float xr10 = __ldg(&g.xg[base1 + c0]);
        float xz10 = __ldg(&g.xg[base1 + 256 + c0]);
        float xn10 = __ldg(&g.xg[base1 + 512 + c0]);
        float xr11 = __ldg(&g.xg[base1 + c1]);
        float xz11 = __ldg(&g.xg[base1 + 256 + c1]);
        float xn11 = __ldg(&g.xg[base1 + 512 + c1]);
        __syncthreads();

        // acc[wrow][seq][parity], f32x2-packed (even-k lane, odd-k lane)
        unsigned long long acc[6][2][2];
#pragma unroll
        for (int i = 0; i < 6; i++)
#pragma unroll
            for (int s = 0; s < 2; s++) { acc[i][s][0] = 0ull; acc[i][s][1] = 0ull; }

#pragma unroll 4
        for (int q = 0; q < 64; q++) {
            ulonglong2 h0 = h0p[q];
            ulonglong2 h1 = h1p[q];
#pragma unroll
            for (int i = 0; i < 6; i++) {
                ulonglong2 w = wp[i][q];
                FMA2(acc[i][0][0], w.x, h0.x); FMA2(acc[i][0][1], w.y, h0.y);
                FMA2(acc[i][1][0], w.x, h1.x); FMA2(acc[i][1][1], w.y, h1.y);
            }
        }
        float aR00 = red2(acc[0][0][0], acc[0][0][1]);
        float aR10 = red2(acc[0][1][0], acc[0][1][1]);
        float aR01 = red2(acc[1][0][0], acc[1][0][1]);
        float aR11 = red2(acc[1][1][0], acc[1][1][1]);
        float aZ00 = red2(acc[2][0][0], acc[2][0][1]);
        float aZ10 = red2(acc[2][1][0], acc[2][1][1]);
        float aZ01 = red2(acc[3][0][0], acc[3][0][1]);
        float aZ11 = red2(acc[3][1][0], acc[3][1][1]);
        float aN00 = red2(acc[4][0][0], acc[4][0][1]);
        float aN10 = red2(acc[4][1][0], acc[4][1][1]);
        float aN01 = red2(acc[5][0][0], acc[5][0][1]);
        float aN11 = red2(acc[5][1][0], acc[5][1][1]);

        // gate math + stores (cells: [seq-half s][col-half c])
#pragma unroll
        for (int s = 0; s < 2; s++) {
            int sl = sj + 8 * s;
            long long seq = sgrp * 16 + sl;
#pragma unroll
            for (int c = 0; c < 2; c++) {
                int col = colbase + ci + 16 * c;
                float aR = s ? (c ? aR11 : aR10) : (c ? aR01 : aR00);
                float aZ = s ? (c ? aZ11 : aZ10) : (c ? aZ01 : aZ00);
                float aN = s ? (c ? aN11 : aN10) : (c ? aN01 : aN00);
                float xr = s ? (c ? xr11 : xr10) : (c ? xr01 : xr00);
                float xz = s ? (c ? xz11 : xz10) : (c ? xz01 : xz00);
                float xn = s ? (c ? xn11 : xn10) : (c ? xn01 : xn00);
                float hr = aR + (c ? br1 : br0);
                float hz = aZ + (c ? bz1 : bz0);
                float hn = aN + (c ? bn1 : bn0);
                float r = 1.f / (1.f + expf(-(xr + hr)));
                float z = 1.f / (1.f + expf(-(xz + hz)));
                float n = tanhf(xn + r * hn);
                float hold = hs[sl * 256 + col];
                float h = (1.f - z) * n + z * hold;
                hout[seq * 256 + col] = h;
                if (g.ys) g.ys[(seq * T + t) * 256 + col] = h;
                if (s) { if (c) mx11 = fmaxf(mx11, h); else mx10 = fmaxf(mx10, h); }
                else   { if (c) mx01 = fmaxf(mx01, h); else mx00 = fmaxf(mx00, h); }
            }
        }
        if (t + 1 < T) group_barrier(flags, mychunk, (unsigned)(t + 1));
    }
    if (g.hmax) {
        long long s0 = sgrp * 16 + sj, s1 = s0 + 8;
        g.hmax[s0 * 256 + c0] = mx00;
        g.hmax[s0 * 256 + c1] = mx01;
        g.hmax[s1 * 256 + c0] = mx10;
        g.hmax[s1 * 256 + c1] = mx11;
    }
}

// ---------------- final: coef gate, feat, output head, softmax over options ----------------
__global__ void __launch_bounds__(512) final_kernel(
    const float* __restrict__ gate_w, const float* __restrict__ gate_b,
    const float* __restrict__ out_w, const float* __restrict__ out_b,
    float* __restrict__ out) {
    __shared__ float coef[128];
    __shared__ float logits[16];
    int tid = threadIdx.x, w = tid >> 5, lane = tid & 31;
    for (int bon = w; bon < 128; bon += 16) {
        float s = 0.f;
        for (int d = lane; d < 512; d += 32) {
            float rv = (d < 256) ? g_srmax[bon * 256 + d] : g_drmax[bon * 256 + d - 256];
            s += rv * gate_w[d];
        }
#pragma unroll
        for (int off = 16; off; off >>= 1) s += __shfl_xor_sync(0xffffffffu, s, off);
        if (lane == 0) coef[bon] = s + gate_b[0];
    }
    __syncthreads();
    {
        int bo = w;
        float acc = 0.f;
        for (int d = lane; d < 1024; d += 32) {
            float v;
            if (d < 512) {
                float mxv = -1e30f;
#pragma unroll
                for (int n = 0; n < 8; n++) {
                    int bon = bo * 8 + n;
                    float rv = (d < 256) ? g_srmax[bon * 256 + d] : g_drmax[bon * 256 + d - 256];
                    mxv = fmaxf(mxv, coef[bon] * rv);
                }
                v = mxv;
            } else {
                int dd = d - 512;
                float smv = 0.f;
#pragma unroll
                for (int n = 0; n < 8; n++) {
                    int bon = bo * 8 + n;
                    float rv = (dd < 256) ? g_srmax[bon * 256 + dd] : g_drmax[bon * 256 + dd - 256];
                    smv += coef[bon] * rv;
                }
                v = smv * 0.125f;
            }
            acc += v * out_w[d];
        }
#pragma unroll
        for (int off = 16; off; off >>= 1) acc += __shfl_xor_sync(0xffffffffu, acc, off);
        if (lane == 0) logits[bo] = acc + out_b[0];
    }
    __syncthreads();
    if (tid < 4) {
        int b = tid;
        float m = -1e30f;
        for (int o = 0; o < 4; o++) m = fmaxf(m, logits[b * 4 + o]);
        float e[4], s = 0.f;
        for (int o = 0; o < 4; o++) { e[o] = expf(logits[b * 4 + o] - m); s += e[o]; }
        for (int o = 0; o < 4; o++) out[b * 4 + o] = e[o] / s;
    }
}

// ---------------- host orchestration ----------------
#define SYM(p, s) do { void* _t = nullptr; cudaGetSymbolAddress(&_t, s); p = (float*)_t; } while (0)

static const int GRU_SMEM = (96 * WP + 16 * 256) * 4;  // 116,224 B

extern "C" void kernel_launch(void* const* d_in, const int* in_sizes, int n_in,
                              void* d_out, int out_size) {
    const float* statement = (const float*)d_in[0];
    const float* answer    = (const float*)d_in[1];
    const float* refs      = (const float*)d_in[2];
    const float* ctx_wih   = (const float*)d_in[3];
    const float* ctx_whh   = (const float*)d_in[4];
    const float* ctx_bih   = (const float*)d_in[5];
    const float* ctx_bhh   = (const float*)d_in[6];
    const float* sr_wih    = (const float*)d_in[7];
    const float* sr_whh    = (const float*)d_in[8];
    const float* sr_bih    = (const float*)d_in[9];
    const float* sr_bhh    = (const float*)d_in[10];
    const float* dr_wih    = (const float*)d_in[11];
    const float* dr_whh    = (const float*)d_in[12];
    const float* dr_bih    = (const float*)d_in[13];
    const float* dr_bhh    = (const float*)d_in[14];
    const float* gate_w    = (const float*)d_in[15];
    const float* gate_b    = (const float*)d_in[16];
    const float* out_w     = (const float*)d_in[17];
    const float* out_b     = (const float*)d_in[18];
    float* out = (float*)d_out;

    float *stmt_in, *xg_stmt, *stmt_h, *xg_docs, *docs_h;
    float *hs0, *hs1, *hd0, *hd1;
    float *matchb, *p1, *p2t, *read_sum, *doc_read, *dri, *mmb, *att;
    float *xg_sr, *xg_dr, *hsr0, *hsr1, *hdr0, *hdr1, *srmax, *drmax;
    SYM(stmt_in, g_stmt_in); SYM(xg_stmt, g_xg_stmt); SYM(stmt_h, g_stmt_h);
    SYM(xg_docs, g_xg_docs); SYM(docs_h, g_docs_h);
    SYM(hs0, g_hs0); SYM(hs1, g_hs1); SYM(hd0, g_hd0); SYM(hd1, g_hd1);
    SYM(matchb, g_match); SYM(p1, g_p1); SYM(p2t, g_p2t);
    SYM(read_sum, g_read_sum); SYM(doc_read, g_doc_read); SYM(dri, g_dri);
    SYM(mmb, g_mm); SYM(att, g_att);
    SYM(xg_sr, g_xg_sr); SYM(xg_dr, g_xg_dr);
    SYM(hsr0, g_hsr0); SYM(hsr1, g_hsr1); SYM(hdr0, g_hdr0); SYM(hdr1, g_hdr1);
    SYM(srmax, g_srmax); SYM(drmax, g_drmax);

    cudaFuncSetAttribute(gru_phase, cudaFuncAttributeMaxDynamicSharedMemorySize, GRU_SMEM);

    init_state<<<128, 256>>>();
    concat_stmt<<<4096, 256>>>(statement, answer);

    // input projections for ctx GRU (TN: W is [768, in])
    gemm_tf32<1><<<dim3(6, 32, 1), 256>>>(stmt_in, ctx_wih, ctx_bih, xg_stmt,
                                          768, 256, 0, 0, 0, 1, 1);
    gemm_tf32<1><<<dim3(6, 128, 1), 256>>>(refs, ctx_wih, ctx_bih, xg_docs,
                                           768, 256, 0, 0, 0, 1, 1);

    // phase A: ctx GRU — stmt (16 seqs, T=256) || docs (128 seqs, T=128)
    {
        GG gs; gs.xg = xg_stmt; gs.whh = ctx_whh; gs.bhh = ctx_bhh;
        gs.h0 = hs0; gs.h1 = hs1; gs.ys = stmt_h; gs.hmax = nullptr;
        gs.T = 256; gs.nsg = 1; gs.slotbase = 0;
        GG gd; gd.xg = xg_docs; gd.whh = ctx_whh; gd.bhh = ctx_bhh;
        gd.h0 = hd0; gd.h1 = hd1; gd.ys = docs_h; gd.hmax = nullptr;
        gd.T = 128; gd.nsg = 8; gd.slotbase = 8;
        gru_phase<<<72, 128, GRU_SMEM>>>(gs, gd);  // 72 blocks, 1/SM
    }

    // match[bon][s][l] = stmt[bo,s,:] . docs[bon,l,:]
    gemm_tf32<1><<<dim3(1, 2, 128), 256>>>(stmt_h, docs_h, nullptr, matchb,
                                           128, 256, 65536, 32768, 32768, 8, 1);
    softmax_warp128<<<4096, 256>>>(matchb, p1);
    softmax_cols_t<<<dim3(32, 128), 128>>>();
    // read_sum = p1 @ docs ; doc_read = p2t @ stmt
    gemm_tf32<0><<<dim3(2, 2, 128), 256>>>(p1, docs_h, nullptr, read_sum,
                                           256, 128, 32768, 32768, 65536, 1, 1);
    gemm_tf32<0><<<dim3(2, 1, 128), 256>>>(p2t, stmt_h, nullptr, doc_read,
                                           256, 256, 32768, 65536, 32768, 1, 8);
    concat_dri<<<4096, 256>>>();

    // doc-doc cross attention per bo: mm = dri @ dri^T ; softmax ; att = p3 @ dri
    gemm_tf32<1><<<dim3(8, 8, 16), 256>>>(dri, dri, nullptr, mmb,
                                          1024, 512, 524288, 524288, 1048576, 1, 1);
    softmax_block1024<<<16384, 256>>>(mmb, mmb);
    gemm_tf32<0><<<dim3(4, 8, 16), 256>>>(mmb, dri, nullptr, att,
                                          512, 1024, 1048576, 524288, 524288, 1, 1);

    // input projections for reasoning GRUs
    gemm_tf32<1><<<dim3(6, 256, 1), 256>>>(read_sum, sr_wih, sr_bih, xg_sr,
                                           768, 256, 0, 0, 0, 1, 1);
    gemm_tf32<1><<<dim3(6, 128, 1), 256>>>(att, dr_wih, dr_bih, xg_dr,
                                           768, 512, 0, 0, 0, 1, 1);

    // phase C: reasoning GRUs — sr (128 seqs, T=256) || dr (128 seqs, T=128)
    {
        GG ga; ga.xg = xg_sr; ga.whh = sr_whh; ga.bhh = sr_bhh;
        ga.h0 = hsr0; ga.h1 = hsr1; ga.ys = nullptr; ga.hmax = srmax;
        ga.T = 256; ga.nsg = 8; ga.slotbase = 32;
        GG gb; gb.xg = xg_dr; gb.whh = dr_whh; gb.bhh = dr_bhh;
        gb.h0 = hdr0; gb.h1 = hdr1; gb.ys = nullptr; gb.hmax = drmax;
        gb.T = 128; gb.nsg = 8; gb.slotbase = 48;
        gru_phase<<<128, 128, GRU_SMEM>>>(ga, gb);  // 128 blocks, 1/SM
    }

    final_kernel<<<1, 512>>>(gate_w, gate_b, out_w, out_b, out);
}

// round 10
// speedup vs baseline: 1.2477x; 1.1542x over previous
#include <cuda_runtime.h>
#include <math.h>

// Problem dims: B=4 O=4 L=128 N=8 V=256 H=256, Ls=2L=256, BO=16, BON=128, NL=1024

// ---------------- scratch (device globals; no allocation allowed) ----------------
__device__ float g_stmt_in[16 * 256 * 256];
__device__ float g_xg_stmt[16 * 256 * 768];
__device__ float g_stmt_h[16 * 256 * 256];
__device__ float g_xg_docs[128 * 128 * 768];
__device__ float g_docs_h[128 * 128 * 256];
__device__ float g_hs0[16 * 256], g_hs1[16 * 256];
__device__ float g_hd0[128 * 256], g_hd1[128 * 256];
__device__ float g_match[128 * 256 * 128];
__device__ float g_p1[128 * 256 * 128];
__device__ float g_p2t[128 * 128 * 256];
__device__ float g_read_sum[128 * 256 * 256];
__device__ float g_doc_read[128 * 128 * 256];
__device__ float g_dri[128 * 128 * 512];
__device__ float g_mm[16 * 1024 * 1024];
__device__ float g_att[128 * 128 * 512];
__device__ float g_xg_sr[128 * 256 * 768];
__device__ float g_xg_dr[128 * 128 * 768];
__device__ float g_hsr0[128 * 256], g_hsr1[128 * 256];
__device__ float g_hdr0[128 * 256], g_hdr1[128 * 256];
__device__ float g_srmax[128 * 256], g_drmax[128 * 256];

// per-(slot, chunk) monotonic step flags: 64 slots x 8 chunks, 128B stride
__device__ unsigned g_flag[64 * 8 * 32];

// ---------------- init ----------------
__global__ void init_state() {
    int i = blockIdx.x * 256 + threadIdx.x;  // 32768 threads
    if (i < 64 * 8 * 32) g_flag[i] = 0u;
    if (i < 16 * 256) { g_hs0[i] = 0.f; g_hs1[i] = 0.f; }
    if (i < 128 * 256) {
        g_hd0[i] = 0.f;  g_hd1[i] = 0.f;
        g_hsr0[i] = 0.f; g_hsr1[i] = 0.f;
        g_hdr0[i] = 0.f; g_hdr1[i] = 0.f;
    }
}

// ---------------- build stmt = cat(question, answer) ----------------
__global__ void concat_stmt(const float* __restrict__ statement,
                            const float* __restrict__ answer) {
    int idx = blockIdx.x * 256 + threadIdx.x;  // 1048576
    int v = idx & 255;
    int s = (idx >> 8) & 255;
    int bo = idx >> 16;
    int b = bo >> 2;
    float val;
    if (s < 128) val = statement[(b * 128 + s) * 256 + v];
    else         val = answer[(bo * 128 + (s - 128)) * 256 + v];
    g_stmt_in[idx] = val;
}

// ---------------- dri = cat(docs, doc_read) ----------------
__global__ void concat_dri() {
    for (int idx = blockIdx.x * blockDim.x + threadIdx.x; idx < 128 * 128 * 512;
         idx += gridDim.x * blockDim.x) {
        int h = idx & 511;
        int rest = idx >> 9;
        g_dri[idx] = (h < 256) ? g_docs_h[rest * 256 + h]
                               : g_doc_read[rest * 256 + (h - 256)];
    }
}

// ---------------- tf32 tensor-core GEMM ----------------
__device__ __forceinline__ unsigned f2tf(float x) {
    unsigned r;
    asm("cvt.rna.tf32.f32 %0, %1;" : "=r"(r) : "f"(x));
    return r;
}

__device__ __forceinline__ void mma_tf32(float4& d, const unsigned* a, const unsigned* b) {
    asm volatile(
        "mma.sync.aligned.m16n8k8.row.col.f32.tf32.tf32.f32 "
        "{%0,%1,%2,%3}, {%4,%5,%6,%7}, {%8,%9}, {%0,%1,%2,%3};"
        : "+f"(d.x), "+f"(d.y), "+f"(d.z), "+f"(d.w)
        : "r"(a[0]), "r"(a[1]), "r"(a[2]), "r"(a[3]), "r"(b[0]), "r"(b[1]));
}

// Tile 128x128, K-tile 32, 256 threads (8 warps, each 64x32).
// TB=1: C = A[M,K] * B[N,K]^T (+bias);  TB=0: C = A[M,K] * B[K,N] (+bias)
template <int TB>
__global__ void __launch_bounds__(256) gemm_tf32(
    const float* __restrict__ A, const float* __restrict__ B,
    const float* __restrict__ bias, float* __restrict__ C,
    int N, int K, long long sA, long long sB, long long sC,
    int divA, int divB) {
    const int tid = threadIdx.x;
    int z = blockIdx.z;
    A += (long long)(z / divA) * sA + (long long)(blockIdx.y * 128) * K;
    if (TB) B += (long long)(z / divB) * sB + (long long)(blockIdx.x * 128) * K;
    else    B += (long long)(z / divB) * sB + blockIdx.x * 128;
    C += (long long)z * sC + (long long)(blockIdx.y * 128) * N + blockIdx.x * 128;

    __shared__ unsigned As[128 * 36];   // [m][k], pitch 36 -> conflict-free frags
    __shared__ unsigned Bs[128 * 36];   // TN: [n][k] pitch 36; NN: [k][n] pitch 132

    const int warp = tid >> 5, lane = tid & 31;
    const int wm = (warp & 1) * 64, wn = (warp >> 1) * 32;
    const int lq = lane >> 2, lr = lane & 3;

    const int sm = tid >> 3;         // 0..31 (row group, +32*i)
    const int sk = (tid & 7) * 4;    // 0..28
    const int bk = tid >> 5;         // 0..7 (NN k row, +8*i)
    const int bn = (tid & 31) * 4;   // 0..124

    float4 acc[4][4];
#pragma unroll
    for (int i = 0; i < 4; i++)
#pragma unroll
        for (int j = 0; j < 4; j++) acc[i][j] = make_float4(0.f, 0.f, 0.f, 0.f);

    float4 pa[4], pb[4];
#pragma unroll
    for (int i = 0; i < 4; i++)
        pa[i] = *reinterpret_cast<const float4*>(&A[(long long)(sm + 32 * i) * K + sk]);
    if (TB) {
#pragma unroll
        for (int i = 0; i < 4; i++)
            pb[i] = *reinterpret_cast<const float4*>(&B[(long long)(sm + 32 * i) * K + sk]);
    } else {
#pragma unroll
        for (int i = 0; i < 4; i++)
            pb[i] = *reinterpret_cast<const float4*>(&B[(long long)(bk + 8 * i) * N + bn]);
    }

    int k0 = 0;
    for (;;) {
#pragma unroll
        for (int i = 0; i < 4; i++) {
            uint4 u;
            u.x = f2tf(pa[i].x); u.y = f2tf(pa[i].y); u.z = f2tf(pa[i].z); u.w = f2tf(pa[i].w);
            *reinterpret_cast<uint4*>(&As[(sm + 32 * i) * 36 + sk]) = u;
        }
#pragma unroll
        for (int i = 0; i < 4; i++) {
            uint4 u;
            u.x = f2tf(pb[i].x); u.y = f2tf(pb[i].y); u.z = f2tf(pb[i].z); u.w = f2tf(pb[i].w);
            if (TB) *reinterpret_cast<uint4*>(&Bs[(sm + 32 * i) * 36 + sk]) = u;
            else    *reinterpret_cast<uint4*>(&Bs[(bk + 8 * i) * 132 + bn]) = u;
        }
        __syncthreads();

        int k1 = k0 + 32;
        if (k1 < K) {
#pragma unroll
            for (int i = 0; i < 4; i++)
                pa[i] = *reinterpret_cast<const float4*>(&A[(long long)(sm + 32 * i) * K + k1 + sk]);
            if (TB) {
#pragma unroll
                for (int i = 0; i < 4; i++)
                    pb[i] = *reinterpret_cast<const float4*>(&B[(long long)(sm + 32 * i) * K + k1 + sk]);
            } else {
#pragma unroll
                for (int i = 0; i < 4; i++)
                    pb[i] = *reinterpret_cast<const float4*>(&B[(long long)(k1 + bk + 8 * i) * N + bn]);
            }
        }

#pragma unroll
        for (int kk = 0; kk < 32; kk += 8) {
            unsigned a[4][4];
#pragma unroll
            for (int mt = 0; mt < 4; mt++) {
                int r = (wm + mt * 16 + lq) * 36 + kk + lr;
                a[mt][0] = As[r];
                a[mt][1] = As[r + 8 * 36];
                a[mt][2] = As[r + 4];
                a[mt][3] = As[r + 8 * 36 + 4];
            }
            unsigned b[4][2];
#pragma unroll
            for (int nt = 0; nt < 4; nt++) {
                if (TB) {
                    int r = (wn + nt * 8 + lq) * 36 + kk + lr;
                    b[nt][0] = Bs[r];
                    b[nt][1] = Bs[r + 4];
                } else {
                    int r = (kk + lr) * 132 + wn + nt * 8 + lq;
                    b[nt][0] = Bs[r];
                    b[nt][1] = Bs[r + 4 * 132];
                }
            }
#pragma unroll
            for (int mt = 0; mt < 4; mt++)
#pragma unroll
                for (int nt = 0; nt < 4; nt++) mma_tf32(acc[mt][nt], a[mt], b[nt]);
        }
        if (k1 >= K) break;
        __syncthreads();
        k0 = k1;
    }

#pragma unroll
    for (int nt = 0; nt < 4; nt++) {
        int col = wn + nt * 8 + 2 * lr;
        float bx = 0.f, by = 0.f;
        if (bias) {
            int cg = blockIdx.x * 128 + col;
            bx = bias[cg]; by = bias[cg + 1];
        }
#pragma unroll
        for (int mt = 0; mt < 4; mt++) {
            int row = wm + mt * 16 + lq;
            float4 v = acc[mt][nt];
            float2 v0 = make_float2(v.x + bx, v.y + by);
            float2 v1 = make_float2(v.z + bx, v.w + by);
            *reinterpret_cast<float2*>(&C[(long long)row * N + col]) = v0;
            *reinterpret_cast<float2*>(&C[(long long)(row + 8) * N + col]) = v1;
        }
    }
}

// ---------------- softmax: 1024 cols, block per row, regs-resident ----------------
__global__ void __launch_bounds__(256) softmax_block1024(const float* __restrict__ in,
                                                         float* __restrict__ out) {
    long long row = blockIdx.x;
    const float4* x = reinterpret_cast<const float4*>(in + row * 1024);
    float4* y = reinterpret_cast<float4*>(out + row * 1024);
    int tid = threadIdx.x, warp = tid >> 5, lane = tid & 31;
    __shared__ float redm[8], reds[8];
    float4 v = x[tid];
    float m = fmaxf(fmaxf(v.x, v.y), fmaxf(v.z, v.w));
#pragma unroll
    for (int off = 16; off; off >>= 1) m = fmaxf(m, __shfl_xor_sync(0xffffffffu, m, off));
    if (lane == 0) redm[warp] = m;
    __syncthreads();
    m = redm[0];
#pragma unroll
    for (int i = 1; i < 8; i++) m = fmaxf(m, redm[i]);
    v.x = __expf(v.x - m); v.y = __expf(v.y - m); v.z = __expf(v.z - m); v.w = __expf(v.w - m);
    float s = v.x + v.y + v.z + v.w;
#pragma unroll
    for (int off = 16; off; off >>= 1) s += __shfl_xor_sync(0xffffffffu, s, off);
    if (lane == 0) reds[warp] = s;
    __syncthreads();
    s = reds[0];
#pragma unroll
    for (int i = 1; i < 8; i++) s += reds[i];
    float inv = 1.f / s;
    v.x *= inv; v.y *= inv; v.z *= inv; v.w *= inv;
    y[tid] = v;
}

// ---------------- softmax: 128 cols, warp per row (8 rows per block) ----------------
__global__ void __launch_bounds__(256) softmax_warp128(const float* __restrict__ in,
                                                       float* __restrict__ out) {
    int warp = threadIdx.x >> 5, lane = threadIdx.x & 31;
    long long row = (long long)blockIdx.x * 8 + warp;
    const float4* x = reinterpret_cast<const float4*>(in + row * 128);
    float4* y = reinterpret_cast<float4*>(out + row * 128);
    float4 v = x[lane];
    float m = fmaxf(fmaxf(v.x, v.y), fmaxf(v.z, v.w));
#pragma unroll
    for (int off = 16; off; off >>= 1) m = fmaxf(m, __shfl_xor_sync(0xffffffffu, m, off));
    v.x = __expf(v.x - m); v.y = __expf(v.y - m); v.z = __expf(v.z - m); v.w = __expf(v.w - m);
    float s = v.x + v.y + v.z + v.w;
#pragma unroll
    for (int off = 16; off; off >>= 1) s += __shfl_xor_sync(0xffffffffu, s, off);
    float inv = 1.f / s;
    v.x *= inv; v.y *= inv; v.z *= inv; v.w *= inv;
    y[lane] = v;
}

// ---------------- column softmax of match over s, output transposed [bon][l][s] ----------------
__global__ void __launch_bounds__(128) softmax_cols_t() {
    int bon = blockIdx.y;
    int l = blockIdx.x * 4 + (threadIdx.x >> 5);
    int lane = threadIdx.x & 31;
    const float* base = g_match + (long long)bon * 256 * 128 + l;
    float v[8];
    float m = -1e30f;
#pragma unroll
    for (int i = 0; i < 8; i++) {
        v[i] = base[(lane + 32 * i) * 128];
        m = fmaxf(m, v[i]);
    }
#pragma unroll
    for (int off = 16; off; off >>= 1) m = fmaxf(m, __shfl_xor_sync(0xffffffffu, m, off));
    float sum = 0.f;
#pragma unroll
    for (int i = 0; i < 8; i++) { v[i] = __expf(v[i] - m); sum += v[i]; }
#pragma unroll
    for (int off = 16; off; off >>= 1) sum += __shfl_xor_sync(0xffffffffu, sum, off);
    float inv = 1.f / sum;
    float* o = g_p2t + ((long long)bon * 128 + l) * 256;
#pragma unroll
    for (int i = 0; i < 8; i++) o[lane + 32 * i] = v[i] * inv;
}

// ---------------- acquire/relaxed flag ops ----------------
__device__ __forceinline__ unsigned ld_acq(const unsigned* p) {
    unsigned v;
    asm volatile("ld.global.acquire.gpu.u32 %0, [%1];" : "=r"(v) : "l"(p) : "memory");
    return v;
}
__device__ __forceinline__ void st_rlx(unsigned* p, unsigned v) {
    asm volatile("st.global.relaxed.gpu.u32 [%0], %1;" :: "l"(p), "r"(v) : "memory");
}

// ---------------- persistent fused GRU phase ----------------
struct GG {
    const float* xg;    // [nseq][T][768]
    const float* whh;   // [768][256]
    const float* bhh;   // [768]
    float* h0;          // [nseq][256] (t even input)
    float* h1;
    float* ys;          // optional [nseq][T][256]
    float* hmax;        // optional [nseq][256]
    int T;
    int nsg;            // seq groups of 16
    int slotbase;       // flag slot base (one slot per sgrp)
};

#define WP 260  // weight row pitch (floats) -> conflict-free 8-row 16B frags
#define HP 260  // h row pitch

// packed fp32x2 FMA (sm_10x): acc{lo,hi} += a{lo,hi} * b{lo,hi}
#define FMA2(acc, a, b) \
    asm("fma.rn.f32x2 %0, %1, %2, %0;" : "+l"(acc) : "l"(a), "l"(b))
#define UNPK(lo, hi, v) \
    asm("mov.b64 {%0,%1}, %2;" : "=f"(lo), "=f"(hi) : "l"(v))

__device__ __forceinline__ float red2(unsigned long long a, unsigned long long b) {
    float l0, h0, l1, h1;
    UNPK(l0, h0, a); UNPK(l1, h1, b);
    return (l0 + h0) + (l1 + h1);
}

// distributed 8-block barrier: each block publishes a monotonic step counter on
// its own flag line; threads 0-7 poll the 8 flags in parallel. No atomics.
__device__ __forceinline__ void group_barrier(unsigned* flags, int mychunk, unsigned tnext) {
    __syncthreads();  // all threads' h stores issued
    int tid = threadIdx.x;
    if (tid < 8) {
        if (tid == 0) {
            __threadfence();                       // order h stores before flag
            st_rlx(&flags[mychunk * 32], tnext);   // publish own step
        }
        while (ld_acq(&flags[tid * 32]) < tnext) {}  // 8 parallel polls
    }
    __syncthreads();
}

// block = 256 threads (8 warps), tile = 16 seqs x 32 cols (one col chunk).
// col-warp cw = warp&3 owns 8 cols; k-warp kw = warp>>2 handles half the k range.
// lane: c8 = lane&7 (col within 8), sq = lane>>3; thread cells = (col, seqs sq+4j).
// Cross-kw partial sums merged through smem once per step.
__global__ void __launch_bounds__(256) gru_phase(GG ga, GG gb) {
    extern __shared__ float sm[];
    float* ws = sm;                         // 96 x WP
    float* hs = sm + 96 * WP;               // 16 x HP
    float* red = sm + 96 * WP + 16 * HP;    // 128 x 13 (pad-13: conflict-free)

    GG g;
    int sgrp, mychunk;
    {
        int b = blockIdx.x;
        int blocks0 = ga.nsg * 8;
        if (b < blocks0) { g = ga; sgrp = b >> 3; mychunk = b & 7; }
        else { g = gb; int bb = b - blocks0; sgrp = bb >> 3; mychunk = bb & 7; }
    }
    const int colbase = mychunk * 32;
    unsigned* flags = &g_flag[(g.slotbase + sgrp) * 8 * 32];
    const int tid = threadIdx.x;
    const int warp = tid >> 5, lane = tid & 31;
    const int kw = warp >> 2, cw = warp & 3;
    const int c8 = lane & 7, sq = lane >> 3;
    const int widx = cw * 8 + c8;   // col within chunk, 0..31
    const int col = colbase + widx;

    // load weight slice: ws row r = gate*32 + j holds whh[gate*256 + colbase + j][:]
    for (int i = tid; i < 96 * 64; i += 256) {
        int r = i >> 6, q = i & 63;
        float4 v = __ldg(reinterpret_cast<const float4*>(
            &g.whh[(long long)((r >> 5) * 256 + colbase + (r & 31)) * 256 + q * 4]));
        *reinterpret_cast<float4*>(&ws[r * WP + q * 4]) = v;
    }
    const float br = g.bhh[col], bz = g.bhh[256 + col], bn = g.bhh[512 + col];
    float mx[4] = {-1e30f, -1e30f, -1e30f, -1e30f};

    const ulonglong2* wR = reinterpret_cast<const ulonglong2*>(&ws[(0  + widx) * WP]);
    const ulonglong2* wZ = reinterpret_cast<const ulonglong2*>(&ws[(32 + widx) * WP]);
    const ulonglong2* wN = reinterpret_cast<const ulonglong2*>(&ws[(64 + widx) * WP]);
    const ulonglong2* hr_[4];
#pragma unroll
    for (int j = 0; j < 4; j++)
        hr_[j] = reinterpret_cast<const ulonglong2*>(&hs[(sq + 4 * j) * HP]);

    const int q0 = kw * 32, q1 = q0 + 32;   // half of the 64 ulonglong2 k-units
    const int T = g.T;
    __syncthreads();  // ws ready

    for (int t = 0; t < T; t++) {
        const float* hin = (t & 1) ? g.h1 : g.h0;
        float* hout = (t & 1) ? g.h0 : g.h1;
        const float4* tb = reinterpret_cast<const float4*>(hin + (long long)sgrp * 16 * 256);
        // stage h tile [16][256]: 1024 float4 over 256 threads
#pragma unroll
        for (int i = 0; i < 4; i++) {
            int idx = tid + i * 256;  // seq = idx>>6, unit = idx&63
            float4 v = __ldcg(tb + idx);
            *reinterpret_cast<float4*>(&hs[(idx >> 6) * HP + (idx & 63) * 4]) = v;
        }
        // xg prefetch (only kw==0 threads consume)
        float xr[4], xz[4], xn[4];
        if (kw == 0) {
#pragma unroll
            for (int j = 0; j < 4; j++) {
                long long base = ((long long)(sgrp * 16 + sq + 4 * j) * T + t) * 768;
                xr[j] = __ldg(&g.xg[base + col]);
                xz[j] = __ldg(&g.xg[base + 256 + col]);
                xn[j] = __ldg(&g.xg[base + 512 + col]);
            }
        }
        __syncthreads();

        unsigned long long aR[4][2], aZ[4][2], aN[4][2];
#pragma unroll
        for (int j = 0; j < 4; j++) {
            aR[j][0] = aR[j][1] = 0ull;
            aZ[j][0] = aZ[j][1] = 0ull;
            aN[j][0] = aN[j][1] = 0ull;
        }
#pragma unroll 4
        for (int q = q0; q < q1; q++) {
            ulonglong2 r_ = wR[q], z_ = wZ[q], n_ = wN[q];
#pragma unroll
            for (int j = 0; j < 4; j++) {
                ulonglong2 h = hr_[j][q];
                FMA2(aR[j][0], r_.x, h.x); FMA2(aR[j][1], r_.y, h.y);
                FMA2(aZ[j][0], z_.x, h.x); FMA2(aZ[j][1], z_.y, h.y);
                FMA2(aN[j][0], n_.x, h.x); FMA2(aN[j][1], n_.y, h.y);
            }
        }
        float pr[4], pz[4], pn[4];
#pragma unroll
        for (int j = 0; j < 4; j++) {
            pr[j] = red2(aR[j][0], aR[j][1]);
            pz[j] = red2(aZ[j][0], aZ[j][1]);
            pn[j] = red2(aN[j][0], aN[j][1]);
        }
        // merge kw halves through smem
        if (kw == 1) {
            float* rp = &red[(tid - 128) * 13];
#pragma unroll
            for (int j = 0; j < 4; j++) {
                rp[j] = pr[j]; rp[4 + j] = pz[j]; rp[8 + j] = pn[j];
            }
        }
        __syncthreads();
        if (kw == 0) {
            const float* rp = &red[tid * 13];
#pragma unroll
            for (int j = 0; j < 4; j++) {
                int sl = sq + 4 * j;
                long long seq = sgrp * 16 + sl;
                float hrv = pr[j] + rp[j] + br;
                float hzv = pz[j] + rp[4 + j] + bz;
                float hnv = pn[j] + rp[8 + j] + bn;
                float r = 1.f / (1.f + expf(-(xr[j] + hrv)));
                float z = 1.f / (1.f + expf(-(xz[j] + hzv)));
                float n = tanhf(xn[j] + r * hnv);
                float hold = hs[sl * HP + col];
                float h = (1.f - z) * n + z * hold;
                hout[seq * 256 + col] = h;
                if (g.ys) g.ys[(seq * T + t) * 256 + col] = h;
                mx[j] = fmaxf(mx[j], h);
            }
        }
        if (t + 1 < T) group_barrier(flags, mychunk, (unsigned)(t + 1));
    }
    if (g.hmax && kw == 0) {
#pragma unroll
        for (int j = 0; j < 4; j++) {
            long long seq = sgrp * 16 + sq + 4 * j;
            g.hmax[seq * 256 + col] = mx[j];
        }
    }
}

// ---------------- final: coef gate, feat, output head, softmax over options ----------------
__global__ void __launch_bounds__(512) final_kernel(
    const float* __restrict__ gate_w, const float* __restrict__ gate_b,
    const float* __restrict__ out_w, const float* __restrict__ out_b,
    float* __restrict__ out) {
    __shared__ float coef[128];
    __shared__ float logits[16];
    int tid = threadIdx.x, w = tid >> 5, lane = tid & 31;
    for (int bon = w; bon < 128; bon += 16) {
        float s = 0.f;
        for (int d = lane; d < 512; d += 32) {
            float rv = (d < 256) ? g_srmax[bon * 256 + d] : g_drmax[bon * 256 + d - 256];
            s += rv * gate_w[d];
        }
#pragma unroll
        for (int off = 16; off; off >>= 1) s += __shfl_xor_sync(0xffffffffu, s, off);
        if (lane == 0) coef[bon] = s + gate_b[0];
    }
    __syncthreads();
    {
        int bo = w;
        float acc = 0.f;
        for (int d = lane; d < 1024; d += 32) {
            float v;
            if (d < 512) {
                float mxv = -1e30f;
#pragma unroll
                for (int n = 0; n < 8; n++) {
                    int bon = bo * 8 + n;
                    float rv = (d < 256) ? g_srmax[bon * 256 + d] : g_drmax[bon * 256 + d - 256];
                    mxv = fmaxf(mxv, coef[bon] * rv);
                }
                v = mxv;
            } else {
                int dd = d - 512;
                float smv = 0.f;
#pragma unroll
                for (int n = 0; n < 8; n++) {
                    int bon = bo * 8 + n;
                    float rv = (dd < 256) ? g_srmax[bon * 256 + dd] : g_drmax[bon * 256 + dd - 256];
                    smv += coef[bon] * rv;
                }
                v = smv * 0.125f;
            }
            acc += v * out_w[d];
        }
#pragma unroll
        for (int off = 16; off; off >>= 1) acc += __shfl_xor_sync(0xffffffffu, acc, off);
        if (lane == 0) logits[bo] = acc + out_b[0];
    }
    __syncthreads();
    if (tid < 4) {
        int b = tid;
        float m = -1e30f;
        for (int o = 0; o < 4; o++) m = fmaxf(m, logits[b * 4 + o]);
        float e[4], s = 0.f;
        for (int o = 0; o < 4; o++) { e[o] = expf(logits[b * 4 + o] - m); s += e[o]; }
        for (int o = 0; o < 4; o++) out[b * 4 + o] = e[o] / s;
    }
}

// ---------------- host orchestration ----------------
#define SYM(p, s) do { void* _t = nullptr; cudaGetSymbolAddress(&_t, s); p = (float*)_t; } while (0)

static const int GRU_SMEM = (96 * WP + 16 * HP + 128 * 13) * 4;  // 123,136 B

extern "C" void kernel_launch(void* const* d_in, const int* in_sizes, int n_in,
                              void* d_out, int out_size) {
    const float* statement = (const float*)d_in[0];
    const float* answer    = (const float*)d_in[1];
    const float* refs      = (const float*)d_in[2];
    const float* ctx_wih   = (const float*)d_in[3];
    const float* ctx_whh   = (const float*)d_in[4];
    const float* ctx_bih   = (const float*)d_in[5];
    const float* ctx_bhh   = (const float*)d_in[6];
    const float* sr_wih    = (const float*)d_in[7];
    const float* sr_whh    = (const float*)d_in[8];
    const float* sr_bih    = (const float*)d_in[9];
    const float* sr_bhh    = (const float*)d_in[10];
    const float* dr_wih    = (const float*)d_in[11];
    const float* dr_whh    = (const float*)d_in[12];
    const float* dr_bih    = (const float*)d_in[13];
    const float* dr_bhh    = (const float*)d_in[14];
    const float* gate_w    = (const float*)d_in[15];
    const float* gate_b    = (const float*)d_in[16];
    const float* out_w     = (const float*)d_in[17];
    const float* out_b     = (const float*)d_in[18];
    float* out = (float*)d_out;

    float *stmt_in, *xg_stmt, *stmt_h, *xg_docs, *docs_h;
    float *hs0, *hs1, *hd0, *hd1;
    float *matchb, *p1, *p2t, *read_sum, *doc_read, *dri, *mmb, *att;
    float *xg_sr, *xg_dr, *hsr0, *hsr1, *hdr0, *hdr1, *srmax, *drmax;
    SYM(stmt_in, g_stmt_in); SYM(xg_stmt, g_xg_stmt); SYM(stmt_h, g_stmt_h);
    SYM(xg_docs, g_xg_docs); SYM(docs_h, g_docs_h);
    SYM(hs0, g_hs0); SYM(hs1, g_hs1); SYM(hd0, g_hd0); SYM(hd1, g_hd1);
    SYM(matchb, g_match); SYM(p1, g_p1); SYM(p2t, g_p2t);
    SYM(read_sum, g_read_sum); SYM(doc_read, g_doc_read); SYM(dri, g_dri);
    SYM(mmb, g_mm); SYM(att, g_att);
    SYM(xg_sr, g_xg_sr); SYM(xg_dr, g_xg_dr);
    SYM(hsr0, g_hsr0); SYM(hsr1, g_hsr1); SYM(hdr0, g_hdr0); SYM(hdr1, g_hdr1);
    SYM(srmax, g_srmax); SYM(drmax, g_drmax);

    cudaFuncSetAttribute(gru_phase, cudaFuncAttributeMaxDynamicSharedMemorySize, GRU_SMEM);

    init_state<<<128, 256>>>();
    concat_stmt<<<4096, 256>>>(statement, answer);

    // input projections for ctx GRU (TN: W is [768, in])
    gemm_tf32<1><<<dim3(6, 32, 1), 256>>>(stmt_in, ctx_wih, ctx_bih, xg_stmt,
                                          768, 256, 0, 0, 0, 1, 1);
    gemm_tf32<1><<<dim3(6, 128, 1), 256>>>(refs, ctx_wih, ctx_bih, xg_docs,
                                           768, 256, 0, 0, 0, 1, 1);

    // phase A: ctx GRU — stmt (16 seqs, T=256) || docs (128 seqs, T=128)
    {
        GG gs; gs.xg = xg_stmt; gs.whh = ctx_whh; gs.bhh = ctx_bhh;
        gs.h0 = hs0; gs.h1 = hs1; gs.ys = stmt_h; gs.hmax = nullptr;
        gs.T = 256; gs.nsg = 1; gs.slotbase = 0;
        GG gd; gd.xg = xg_docs; gd.whh = ctx_whh; gd.bhh = ctx_bhh;
        gd.h0 = hd0; gd.h1 = hd1; gd.ys = docs_h; gd.hmax = nullptr;
        gd.T = 128; gd.nsg = 8; gd.slotbase = 8;
        gru_phase<<<72, 256, GRU_SMEM>>>(gs, gd);  // 72 blocks, 1/SM
    }

    // match[bon][s][l] = stmt[bo,s,:] . docs[bon,l,:]
    gemm_tf32<1><<<dim3(1, 2, 128), 256>>>(stmt_h, docs_h, nullptr, matchb,
                                           128, 256, 65536, 32768, 32768, 8, 1);
    softmax_warp128<<<4096, 256>>>(matchb, p1);
    softmax_cols_t<<<dim3(32, 128), 128>>>();
    // read_sum = p1 @ docs ; doc_read = p2t @ stmt
    gemm_tf32<0><<<dim3(2, 2, 128), 256>>>(p1, docs_h, nullptr, read_sum,
                                           256, 128, 32768, 32768, 65536, 1, 1);
    gemm_tf32<0><<<dim3(2, 1, 128), 256>>>(p2t, stmt_h, nullptr, doc_read,
                                           256, 256, 32768, 65536, 32768, 1, 8);
    concat_dri<<<4096, 256>>>();

    // doc-doc cross attention per bo: mm = dri @ dri^T ; softmax ; att = p3 @ dri
    gemm_tf32<1><<<dim3(8, 8, 16), 256>>>(dri, dri, nullptr, mmb,
                                          1024, 512, 524288, 524288, 1048576, 1, 1);
    softmax_block1024<<<16384, 256>>>(mmb, mmb);
    gemm_tf32<0><<<dim3(4, 8, 16), 256>>>(mmb, dri, nullptr, att,
                                          512, 1024, 1048576, 524288, 524288, 1, 1);

    // input projections for reasoning GRUs
    gemm_tf32<1><<<dim3(6, 256, 1), 256>>>(read_sum, sr_wih, sr_bih, xg_sr,
                                           768, 256, 0, 0, 0, 1, 1);
    gemm_tf32<1><<<dim3(6, 128, 1), 256>>>(att, dr_wih, dr_bih, xg_dr,
                                           768, 512, 0, 0, 0, 1, 1);

    // phase C: reasoning GRUs — sr (128 seqs, T=256) || dr (128 seqs, T=128)
    {
        GG ga; ga.xg = xg_sr; ga.whh = sr_whh; ga.bhh = sr_bhh;
        ga.h0 = hsr0; ga.h1 = hsr1; ga.ys = nullptr; ga.hmax = srmax;
        ga.T = 256; ga.nsg = 8; ga.slotbase = 32;
        GG gb; gb.xg = xg_dr; gb.whh = dr_whh; gb.bhh = dr_bhh;
        gb.h0 = hdr0; gb.h1 = hdr1; gb.ys = nullptr; gb.hmax = drmax;
        gb.T = 128; gb.nsg = 8; gb.slotbase = 48;
        gru_phase<<<128, 256, GRU_SMEM>>>(ga, gb);  // 128 blocks, 1/SM
    }

    final_kernel<<<1, 512>>>(gate_w, gate_b, out_w, out_b, out);
}